// round 2
// baseline (speedup 1.0000x reference)
#include <cuda_runtime.h>
#include <cuda_bf16.h>
#include <math.h>

// ---------------------------------------------------------------------------
// SAM ViT-B image encoder, fp32 SIMT baseline v2.
//  - 128x128x16 / 8x8-frag SGEMM for dense layers (1 B/FMA smem balance)
//  - 64x64x16 / 4x4-frag GEMM for small-N (attn@v) and tiny grids
//  - fused bias / GELU / residual epilogues, composite window*head batching
// ---------------------------------------------------------------------------

#define GF_BIAS 1
#define GF_ADD  2
#define GF_GELU 4

// ---------------- scratch (static device memory; no allocation) ------------
__device__ float g_A[1024 * 2304];        // im2col scratch (patch + neck conv3x3)
__device__ float g_h[1024 * 768];         // residual stream
__device__ float g_t[1024 * 768];         // LN output
__device__ float g_w[9 * 196 * 768];      // window-partitioned tokens
__device__ float g_qkv[9 * 196 * 2304];   // fused qkv (window worst case 1764 tokens)
__device__ float g_sc[12 * 1024 * 1024];  // attention scores (global worst case)
__device__ float g_rh[12 * 1024 * 32];    // rel-h dot products
__device__ float g_rw[12 * 1024 * 32];    // rel-w dot products
__device__ float g_ao[9 * 196 * 768];     // attention output (window layout)
__device__ float g_u[1024 * 768];         // un-partitioned attention output
__device__ float g_mlp[1024 * 3072];      // MLP hidden
__device__ float g_n1[1024 * 256];        // neck scratch 1
__device__ float g_n2[1024 * 256];        // neck scratch 2

// ---------------- 128x128x16 SGEMM (8x8 fragments) --------------------------
// C = op(A[M,K]) @ op(B) (+bias)(gelu?)(+=C?)
// batch offset = (z / HB) * s1 + (z % HB) * s2
template <int TRANSB>
__global__ __launch_bounds__(256) void gemm128_kernel(
    const float* __restrict__ A, const float* __restrict__ B,
    float* __restrict__ C, const float* __restrict__ bias,
    int M, int N, int K, int lda, int ldb, int ldc,
    int HB, long long sA1, long long sA2, long long sB1, long long sB2,
    long long sC1, long long sC2, int flags)
{
    __shared__ __align__(16) float As[16][132];
    __shared__ __align__(16) float Bs[16][132];

    int z = blockIdx.z;
    int zw = z / HB, zh = z % HB;
    A += zw * sA1 + zh * sA2;
    B += zw * sB1 + zh * sB2;
    C += zw * sC1 + zh * sC2;

    int bm = blockIdx.y * 128, bn = blockIdx.x * 128;
    int tid = threadIdx.x;
    int tx = tid & 15, ty = tid >> 4;   // 16x16 thread grid, 8x8 frag each

    float acc[8][8];
#pragma unroll
    for (int i = 0; i < 8; i++)
#pragma unroll
        for (int j = 0; j < 8; j++) acc[i][j] = 0.f;

    for (int k0 = 0; k0 < K; k0 += 16) {
        // A tile (128 rows x 16 k) -> As[k][m]
#pragma unroll
        for (int i = 0; i < 8; i++) {
            int e = tid + i * 256;
            int r = e >> 4, c = e & 15;
            int gm = bm + r, gk = k0 + c;
            As[c][r] = (gm < M && gk < K) ? A[(size_t)gm * lda + gk] : 0.f;
        }
        if (!TRANSB) {
#pragma unroll
            for (int i = 0; i < 8; i++) {
                int e = tid + i * 256;
                int r = e >> 7, c = e & 127;
                int gk = k0 + r, gn = bn + c;
                Bs[r][c] = (gk < K && gn < N) ? B[(size_t)gk * ldb + gn] : 0.f;
            }
        } else {
#pragma unroll
            for (int i = 0; i < 8; i++) {
                int e = tid + i * 256;
                int n = e >> 4, c = e & 15;
                int gn = bn + n, gk = k0 + c;
                Bs[c][n] = (gn < N && gk < K) ? B[(size_t)gn * ldb + gk] : 0.f;
            }
        }
        __syncthreads();
#pragma unroll
        for (int kk = 0; kk < 16; kk++) {
            float4 a0 = *(const float4*)&As[kk][ty * 8];
            float4 a1 = *(const float4*)&As[kk][ty * 8 + 4];
            float4 b0 = *(const float4*)&Bs[kk][tx * 8];
            float4 b1 = *(const float4*)&Bs[kk][tx * 8 + 4];
            float a[8] = {a0.x, a0.y, a0.z, a0.w, a1.x, a1.y, a1.z, a1.w};
            float b[8] = {b0.x, b0.y, b0.z, b0.w, b1.x, b1.y, b1.z, b1.w};
#pragma unroll
            for (int i = 0; i < 8; i++)
#pragma unroll
                for (int j = 0; j < 8; j++) acc[i][j] = fmaf(a[i], b[j], acc[i][j]);
        }
        __syncthreads();
    }

#pragma unroll
    for (int i = 0; i < 8; i++) {
        int gm = bm + ty * 8 + i;
        if (gm >= M) continue;
#pragma unroll
        for (int j = 0; j < 8; j++) {
            int gn = bn + tx * 8 + j;
            if (gn >= N) continue;
            float v = acc[i][j];
            if (flags & GF_BIAS) v += bias[gn];
            if (flags & GF_GELU) v = 0.5f * v * (1.f + erff(v * 0.70710678118654752f));
            size_t off = (size_t)gm * ldc + gn;
            if (flags & GF_ADD) v += C[off];
            C[off] = v;
        }
    }
}

// ---------------- 64x64x16 GEMM (4x4 fragments) ------------------------------
template <int TRANSB>
__global__ __launch_bounds__(256) void gemm64_kernel(
    const float* __restrict__ A, const float* __restrict__ B,
    float* __restrict__ C, const float* __restrict__ bias,
    int M, int N, int K, int lda, int ldb, int ldc,
    int HB, long long sA1, long long sA2, long long sB1, long long sB2,
    long long sC1, long long sC2, int flags)
{
    __shared__ __align__(16) float As[16][68];
    __shared__ __align__(16) float Bs[16][68];

    int z = blockIdx.z;
    int zw = z / HB, zh = z % HB;
    A += zw * sA1 + zh * sA2;
    B += zw * sB1 + zh * sB2;
    C += zw * sC1 + zh * sC2;

    int bm = blockIdx.y * 64, bn = blockIdx.x * 64;
    int tid = threadIdx.x;
    int tx = tid & 15, ty = tid >> 4;

    float acc[4][4];
#pragma unroll
    for (int i = 0; i < 4; i++)
#pragma unroll
        for (int j = 0; j < 4; j++) acc[i][j] = 0.f;

    for (int k0 = 0; k0 < K; k0 += 16) {
#pragma unroll
        for (int i = 0; i < 4; i++) {
            int e = tid + i * 256;
            int r = e >> 4, c = e & 15;
            int gm = bm + r, gk = k0 + c;
            As[c][r] = (gm < M && gk < K) ? A[(size_t)gm * lda + gk] : 0.f;
        }
        if (!TRANSB) {
#pragma unroll
            for (int i = 0; i < 4; i++) {
                int e = tid + i * 256;
                int r = e >> 6, c = e & 63;
                int gk = k0 + r, gn = bn + c;
                Bs[r][c] = (gk < K && gn < N) ? B[(size_t)gk * ldb + gn] : 0.f;
            }
        } else {
#pragma unroll
            for (int i = 0; i < 4; i++) {
                int e = tid + i * 256;
                int n = e >> 4, c = e & 15;
                int gn = bn + n, gk = k0 + c;
                Bs[c][n] = (gn < N && gk < K) ? B[(size_t)gn * ldb + gk] : 0.f;
            }
        }
        __syncthreads();
#pragma unroll
        for (int kk = 0; kk < 16; kk++) {
            float4 av = *(const float4*)&As[kk][ty * 4];
            float4 bv = *(const float4*)&Bs[kk][tx * 4];
            float a[4] = {av.x, av.y, av.z, av.w};
            float b[4] = {bv.x, bv.y, bv.z, bv.w};
#pragma unroll
            for (int i = 0; i < 4; i++)
#pragma unroll
                for (int j = 0; j < 4; j++) acc[i][j] = fmaf(a[i], b[j], acc[i][j]);
        }
        __syncthreads();
    }

#pragma unroll
    for (int i = 0; i < 4; i++) {
        int gm = bm + ty * 4 + i;
        if (gm >= M) continue;
#pragma unroll
        for (int j = 0; j < 4; j++) {
            int gn = bn + tx * 4 + j;
            if (gn >= N) continue;
            float v = acc[i][j];
            if (flags & GF_BIAS) v += bias[gn];
            if (flags & GF_GELU) v = 0.5f * v * (1.f + erff(v * 0.70710678118654752f));
            size_t off = (size_t)gm * ldc + gn;
            if (flags & GF_ADD) v += C[off];
            C[off] = v;
        }
    }
}

// ---------------- LayerNorm -------------------------------------------------
__global__ void ln_kernel(const float* __restrict__ in, float* __restrict__ out,
                          const float* __restrict__ w, const float* __restrict__ bb,
                          int C, float eps)
{
    int row = blockIdx.x;
    const float* xr = in + (size_t)row * C;
    float* yr = out + (size_t)row * C;
    float s = 0.f, s2 = 0.f;
    for (int i = threadIdx.x; i < C; i += blockDim.x) {
        float v = xr[i]; s += v; s2 += v * v;
    }
    __shared__ float shs[8], shq[8];
#pragma unroll
    for (int o = 16; o > 0; o >>= 1) {
        s  += __shfl_down_sync(0xffffffffu, s, o);
        s2 += __shfl_down_sync(0xffffffffu, s2, o);
    }
    int wid = threadIdx.x >> 5;
    if ((threadIdx.x & 31) == 0) { shs[wid] = s; shq[wid] = s2; }
    __syncthreads();
    if (threadIdx.x == 0) {
        float a = 0.f, b2 = 0.f;
        for (int k = 0; k < 8; k++) { a += shs[k]; b2 += shq[k]; }
        shs[0] = a; shq[0] = b2;
    }
    __syncthreads();
    float mean = shs[0] / C;
    float var = shq[0] / C - mean * mean;
    float inv = rsqrtf(fmaxf(var, 0.f) + eps);
    for (int i = threadIdx.x; i < C; i += blockDim.x)
        yr[i] = (xr[i] - mean) * inv * w[i] + bb[i];
}

// ---------------- decomposed rel-pos dot products ---------------------------
// out[z][qi][kk] = dot64( q[z,qi,:], table[qc - kk + S - 1] )
// mode 0: qc = qi / W ; mode 1: qc = qi % W
__global__ void reldot_kernel(const float* __restrict__ qkv,
                              const float* __restrict__ table,
                              float* __restrict__ out,
                              int N, int W, int S, int mode, int B)
{
    long long idx = (long long)blockIdx.x * blockDim.x + threadIdx.x;
    long long total = (long long)B * N * S;
    if (idx >= total) return;
    int kk = (int)(idx % S);
    long long t = idx / S;
    int qi = (int)(t % N);
    int z = (int)(t / N);
    int qc = mode ? (qi % W) : (qi / W);
    const float* q = qkv + (size_t)(z / 12) * N * 2304 + (size_t)qi * 2304 + (z % 12) * 64;
    const float* r = table + (size_t)(qc - kk + S - 1) * 64;
    float acc = 0.f;
#pragma unroll
    for (int d = 0; d < 64; d++) acc += q[d] * r[d];
    out[idx] = acc;
}

// ---------------- softmax with fused scale + rel terms ----------------------
__global__ void softmax_rel_kernel(float* __restrict__ S,
                                   const float* __restrict__ relh,
                                   const float* __restrict__ relw,
                                   int N, int H, int W, float scale)
{
    int qi = blockIdx.x;
    int z = blockIdx.y;
    float* row = S + ((size_t)z * N + qi) * (size_t)N;
    const float* rh = relh + ((size_t)z * N + qi) * H;
    const float* rw = relw + ((size_t)z * N + qi) * W;

    __shared__ float sh[8];
    float mx = -1e30f;
    for (int i = threadIdx.x; i < N; i += blockDim.x) {
        float v = row[i] * scale + rh[i / W] + rw[i % W];
        row[i] = v;
        mx = fmaxf(mx, v);
    }
#pragma unroll
    for (int o = 16; o > 0; o >>= 1) mx = fmaxf(mx, __shfl_down_sync(0xffffffffu, mx, o));
    int wid = threadIdx.x >> 5;
    if ((threadIdx.x & 31) == 0) sh[wid] = mx;
    __syncthreads();
    if (threadIdx.x == 0) {
        float a = -1e30f;
        for (int k = 0; k < 8; k++) a = fmaxf(a, sh[k]);
        sh[0] = a;
    }
    __syncthreads();
    float m = sh[0];
    __syncthreads();

    float sum = 0.f;
    for (int i = threadIdx.x; i < N; i += blockDim.x) {
        float e = __expf(row[i] - m);
        row[i] = e;
        sum += e;
    }
#pragma unroll
    for (int o = 16; o > 0; o >>= 1) sum += __shfl_down_sync(0xffffffffu, sum, o);
    if ((threadIdx.x & 31) == 0) sh[wid] = sum;
    __syncthreads();
    if (threadIdx.x == 0) {
        float a = 0.f;
        for (int k = 0; k < 8; k++) a += sh[k];
        sh[0] = a;
    }
    __syncthreads();
    float inv = 1.f / sh[0];
    for (int i = threadIdx.x; i < N; i += blockDim.x) row[i] *= inv;
}

// ---------------- layout kernels --------------------------------------------
__global__ void im2col_patch_kernel(const float* __restrict__ x, float* __restrict__ A)
{
    int idx = blockIdx.x * blockDim.x + threadIdx.x;
    if (idx >= 1024 * 768) return;
    int k = idx % 768, p = idx / 768;
    int c = k % 3, tkk = k / 3;
    int pw = tkk % 16, ph = tkk / 16;
    int py = p / 32, px = p % 32;
    A[idx] = x[(size_t)c * 512 * 512 + (size_t)(py * 16 + ph) * 512 + (px * 16 + pw)];
}

__global__ void winpart_kernel(const float* __restrict__ in, float* __restrict__ out)
{
    int idx = blockIdx.x * blockDim.x + threadIdx.x;
    if (idx >= 9 * 196 * 768) return;
    int c = idx % 768;
    int t = idx / 768;
    int n = t % 196, w = t / 196;
    int wy = n / 14, wx = n % 14;
    int wr = w / 3, wc = w % 3;
    int y = wr * 14 + wy, x = wc * 14 + wx;
    out[idx] = (y < 32 && x < 32) ? in[((size_t)y * 32 + x) * 768 + c] : 0.f;
}

__global__ void winunpart_kernel(const float* __restrict__ in, float* __restrict__ out)
{
    int idx = blockIdx.x * blockDim.x + threadIdx.x;
    if (idx >= 1024 * 768) return;
    int c = idx % 768;
    int t = idx / 768;
    int y = t / 32, x = t % 32;
    int w = (y / 14) * 3 + (x / 14);
    int n = (y % 14) * 14 + (x % 14);
    out[idx] = in[((size_t)w * 196 + n) * 768 + c];
}

__global__ void im2col3_kernel(const float* __restrict__ in, float* __restrict__ A)
{
    int idx = blockIdx.x * blockDim.x + threadIdx.x;
    if (idx >= 1024 * 2304) return;
    int k = idx % 2304, p = idx / 2304;
    int ic = k % 256, t = k / 256;
    int kx = t % 3, ky = t / 3;
    int y = p / 32 + ky - 1, x = p % 32 + kx - 1;
    A[idx] = (y >= 0 && y < 32 && x >= 0 && x < 32)
                 ? in[((size_t)y * 32 + x) * 256 + ic] : 0.f;
}

__global__ void transpose_out_kernel(const float* __restrict__ in, float* __restrict__ out)
{
    int idx = blockIdx.x * blockDim.x + threadIdx.x;
    if (idx >= 256 * 1024) return;
    int yx = idx % 1024, c = idx / 1024;
    out[idx] = in[(size_t)yx * 256 + c];
}

// ---------------- host orchestration ----------------------------------------
static inline void gemm(const float* Ap, const float* Bp, float* Cp, const float* bias,
                        int M, int N, int K, int lda, int ldb, int ldc,
                        int batches, int HB,
                        long long sA1, long long sA2, long long sB1, long long sB2,
                        long long sC1, long long sC2, int flags, bool transb)
{
    long long big_blocks = (long long)((M + 127) / 128) * ((N + 127) / 128) * batches;
    bool big = (N > 64) && (big_blocks >= 24);
    if (big) {
        dim3 grid((N + 127) / 128, (M + 127) / 128, batches);
        if (transb)
            gemm128_kernel<1><<<grid, 256>>>(Ap, Bp, Cp, bias, M, N, K, lda, ldb, ldc,
                                             HB, sA1, sA2, sB1, sB2, sC1, sC2, flags);
        else
            gemm128_kernel<0><<<grid, 256>>>(Ap, Bp, Cp, bias, M, N, K, lda, ldb, ldc,
                                             HB, sA1, sA2, sB1, sB2, sC1, sC2, flags);
    } else {
        dim3 grid((N + 63) / 64, (M + 63) / 64, batches);
        if (transb)
            gemm64_kernel<1><<<grid, 256>>>(Ap, Bp, Cp, bias, M, N, K, lda, ldb, ldc,
                                            HB, sA1, sA2, sB1, sB2, sC1, sC2, flags);
        else
            gemm64_kernel<0><<<grid, 256>>>(Ap, Bp, Cp, bias, M, N, K, lda, ldb, ldc,
                                            HB, sA1, sA2, sB1, sB2, sC1, sC2, flags);
    }
}

extern "C" void kernel_launch(void* const* d_in, const int* in_sizes, int n_in,
                              void* d_out, int out_size)
{
    (void)in_sizes; (void)n_in; (void)out_size;
    const float* x       = (const float*)d_in[0];
    const float* patch_w = (const float*)d_in[1];
    const float* patch_b = (const float*)d_in[2];
    const float* pos     = (const float*)d_in[3];
    const float* ln1_w   = (const float*)d_in[4];
    const float* ln1_b   = (const float*)d_in[5];
    const float* qkv_w   = (const float*)d_in[6];
    const float* qkv_b   = (const float*)d_in[7];
    const float* proj_w  = (const float*)d_in[8];
    const float* proj_b  = (const float*)d_in[9];
    const float* ln2_w   = (const float*)d_in[10];
    const float* ln2_b   = (const float*)d_in[11];
    const float* fc1_w   = (const float*)d_in[12];
    const float* fc1_b   = (const float*)d_in[13];
    const float* fc2_w   = (const float*)d_in[14];
    const float* fc2_b   = (const float*)d_in[15];
    const float* rhw     = (const float*)d_in[16];
    const float* rww     = (const float*)d_in[17];
    const float* rhg     = (const float*)d_in[18];
    const float* rwg     = (const float*)d_in[19];
    const float* neck_w1 = (const float*)d_in[20];
    const float* nln1w   = (const float*)d_in[21];
    const float* nln1b   = (const float*)d_in[22];
    const float* neck_w2 = (const float*)d_in[23];
    const float* nln2w   = (const float*)d_in[24];
    const float* nln2b   = (const float*)d_in[25];

    float *A, *h, *t, *w, *qkv, *sc, *rh, *rw, *ao, *u, *mlp, *n1, *n2;
    cudaGetSymbolAddress((void**)&A,   g_A);
    cudaGetSymbolAddress((void**)&h,   g_h);
    cudaGetSymbolAddress((void**)&t,   g_t);
    cudaGetSymbolAddress((void**)&w,   g_w);
    cudaGetSymbolAddress((void**)&qkv, g_qkv);
    cudaGetSymbolAddress((void**)&sc,  g_sc);
    cudaGetSymbolAddress((void**)&rh,  g_rh);
    cudaGetSymbolAddress((void**)&rw,  g_rw);
    cudaGetSymbolAddress((void**)&ao,  g_ao);
    cudaGetSymbolAddress((void**)&u,   g_u);
    cudaGetSymbolAddress((void**)&mlp, g_mlp);
    cudaGetSymbolAddress((void**)&n1,  g_n1);
    cudaGetSymbolAddress((void**)&n2,  g_n2);

    const int T = 256;

    // ---- patch embed + pos_embed ----
    im2col_patch_kernel<<<(1024 * 768 + T - 1) / T, T>>>(x, A);
    cudaMemcpyAsync(h, pos, (size_t)1024 * 768 * sizeof(float),
                    cudaMemcpyDeviceToDevice, 0);
    gemm(A, patch_w, h, patch_b, 1024, 768, 768, 768, 768, 768,
         1, 1, 0, 0, 0, 0, 0, 0, GF_BIAS | GF_ADD, false);

    int wi = 0, gi = 0;
    for (int i = 0; i < 12; i++) {
        bool glob = (i == 2 || i == 5 || i == 8 || i == 11);
        int nw = glob ? 1 : 9;
        int N = glob ? 1024 : 196;
        int Hd = glob ? 32 : 14;          // H == W
        int tokens = nw * N;
        int B = nw * 12;

        // LN1
        ln_kernel<<<1024, T>>>(h, t, ln1_w + i * 768, ln1_b + i * 768, 768, 1e-5f);

        // window partition (padded tokens DO go through qkv, like the reference)
        const float* src = t;
        if (!glob) {
            winpart_kernel<<<(tokens * 768 + T - 1) / T, T>>>(t, w);
            src = w;
        }

        // fused qkv GEMM
        gemm(src, qkv_w + (size_t)i * 768 * 2304, qkv, qkv_b + (size_t)i * 2304,
             tokens, 2304, 768, 768, 2304, 2304,
             1, 1, 0, 0, 0, 0, 0, 0, GF_BIAS, false);

        // decomposed rel-pos dot products (unscaled q)
        const float* th = glob ? rhg + (size_t)gi * 63 * 64 : rhw + (size_t)wi * 27 * 64;
        const float* tw = glob ? rwg + (size_t)gi * 63 * 64 : rww + (size_t)wi * 27 * 64;
        long long tot = (long long)B * N * Hd;
        reldot_kernel<<<(unsigned)((tot + T - 1) / T), T>>>(qkv, th, rh, N, Hd, Hd, 0, B);
        reldot_kernel<<<(unsigned)((tot + T - 1) / T), T>>>(qkv, tw, rw, N, Hd, Hd, 1, B);

        // scores = q @ k^T  (batched NT over windows x heads)
        gemm(qkv, qkv + 768, sc, nullptr, N, N, 64, 2304, 2304, N,
             B, 12,
             (long long)N * 2304, 64, (long long)N * 2304, 64,
             12LL * N * N, (long long)N * N, 0, true);

        // softmax(scale * scores + relh + relw)
        softmax_rel_kernel<<<dim3(N, B), T>>>(sc, rh, rw, N, Hd, Hd, 0.125f);

        // attn @ v -> per-head columns of (tokens, 768)
        gemm(sc, qkv + 2 * 768, ao, nullptr, N, 64, N, N, 2304, 768,
             B, 12,
             12LL * N * N, (long long)N * N,
             (long long)N * 2304, 64,
             (long long)N * 768, 64, 0, false);

        // un-partition (drop padding), then proj with residual add
        const float* po = ao;
        if (!glob) {
            winunpart_kernel<<<(1024 * 768 + T - 1) / T, T>>>(ao, u);
            po = u;
        }
        gemm(po, proj_w + (size_t)i * 768 * 768, h, proj_b + (size_t)i * 768,
             1024, 768, 768, 768, 768, 768,
             1, 1, 0, 0, 0, 0, 0, 0, GF_BIAS | GF_ADD, false);

        // MLP
        ln_kernel<<<1024, T>>>(h, t, ln2_w + i * 768, ln2_b + i * 768, 768, 1e-5f);
        gemm(t, fc1_w + (size_t)i * 768 * 3072, mlp, fc1_b + (size_t)i * 3072,
             1024, 3072, 768, 768, 3072, 3072,
             1, 1, 0, 0, 0, 0, 0, 0, GF_BIAS | GF_GELU, false);
        gemm(mlp, fc2_w + (size_t)i * 3072 * 768, h, fc2_b + (size_t)i * 768,
             1024, 768, 3072, 3072, 768, 768,
             1, 1, 0, 0, 0, 0, 0, 0, GF_BIAS | GF_ADD, false);

        if (glob) gi++; else wi++;
    }

    // ---- neck ----
    gemm(h, neck_w1, n1, nullptr, 1024, 256, 768, 768, 256, 256,
         1, 1, 0, 0, 0, 0, 0, 0, 0, false);
    ln_kernel<<<1024, T>>>(n1, n2, nln1w, nln1b, 256, 1e-6f);
    im2col3_kernel<<<(1024 * 2304 + T - 1) / T, T>>>(n2, A);
    gemm(A, neck_w2, n1, nullptr, 1024, 256, 2304, 2304, 256, 256,
         1, 1, 0, 0, 0, 0, 0, 0, 0, false);
    ln_kernel<<<1024, T>>>(n1, n2, nln2w, nln2b, 256, 1e-6f);
    transpose_out_kernel<<<(256 * 1024 + T - 1) / T, T>>>(n2, (float*)d_out);
}

// round 4
// speedup vs baseline: 1.6282x; 1.6282x over previous
#include <cuda_runtime.h>
#include <cuda_bf16.h>
#include <math.h>
#include <stdint.h>

typedef __nv_bfloat16 bf16;

#define GF_BIAS 1
#define GF_ADD  2
#define GF_GELU 4

// ---------------- fp32 scratch ----------------------------------------------
__device__ float g_A[1024 * 2304];
__device__ float g_h[1024 * 768];
__device__ float g_t[1024 * 768];
__device__ float g_w[9 * 196 * 768];
__device__ float g_qkv[9 * 196 * 2304];
__device__ float g_sc[12 * 1024 * 1024];
__device__ float g_rh[12 * 1024 * 32];
__device__ float g_rw[12 * 1024 * 32];
__device__ float g_ao[9 * 196 * 768];
__device__ float g_u[1024 * 768];
__device__ float g_mlp[1024 * 3072];
__device__ float g_n1[1024 * 256];
__device__ float g_n2[1024 * 256];

// ---------------- bf16 hi/lo buffers ----------------------------------------
__device__ bf16 g_wq_h[12 * 2304 * 768],  g_wq_l[12 * 2304 * 768];
__device__ bf16 g_wp_h[12 * 768 * 768],   g_wp_l[12 * 768 * 768];
__device__ bf16 g_w1_h[12 * 3072 * 768],  g_w1_l[12 * 3072 * 768];
__device__ bf16 g_w2_h[12 * 768 * 3072],  g_w2_l[12 * 768 * 3072];
__device__ bf16 g_wpt_h[768 * 768],       g_wpt_l[768 * 768];
__device__ bf16 g_wn1_h[256 * 768],       g_wn1_l[256 * 768];
__device__ bf16 g_wn2_h[256 * 2304],      g_wn2_l[256 * 2304];
__device__ bf16 g_act_h[9 * 196 * 768],   g_act_l[9 * 196 * 768];
__device__ bf16 g_qb_h[9 * 196 * 2304],   g_qb_l[9 * 196 * 2304];
__device__ bf16 g_at_h[12 * 1024 * 1024], g_at_l[12 * 1024 * 1024];
__device__ bf16 g_vt_h[108 * 64 * 196],   g_vt_l[108 * 64 * 196];
__device__ bf16 g_col_h[1024 * 2304],     g_col_l[1024 * 2304];
__device__ bf16 g_mb_h[1024 * 3072],      g_mb_l[1024 * 3072];
__device__ bf16 g_ub_h[1024 * 768],       g_ub_l[1024 * 768];

// ---------------- mma helper -------------------------------------------------
#define MMA_BF16(c, a, b) \
    asm volatile("mma.sync.aligned.m16n8k16.row.col.f32.bf16.bf16.f32 " \
                 "{%0,%1,%2,%3}, {%4,%5,%6,%7}, {%8,%9}, {%0,%1,%2,%3};\n" \
                 : "+f"((c)[0]), "+f"((c)[1]), "+f"((c)[2]), "+f"((c)[3]) \
                 : "r"((a)[0]), "r"((a)[1]), "r"((a)[2]), "r"((a)[3]), \
                   "r"((b)[0]), "r"((b)[1]))

// ---------------- split-bf16 batched GEMM ------------------------------------
// C[M,N] = A[M,K] * B^T where A layout [m][k] (lda), B layout [n][k] (ldb).
// Split precision: acc = Ah*Bh + Ah*Bl + Al*Bh  (fp32 accumulate).
// batch offset = (z / HB)*s1 + (z % HB)*s2 per operand.
template <int BN, int WARPS_M, int WARPS_N, int WM, int WN>
__global__ __launch_bounds__(256) void gemm_mma_kernel(
    const bf16* __restrict__ Ah, const bf16* __restrict__ Al,
    const bf16* __restrict__ Bh, const bf16* __restrict__ Bl,
    float* __restrict__ C, const float* __restrict__ bias,
    int M, int N, int K, int lda, int ldb, int ldc,
    int HB, long long sA1, long long sA2, long long sB1, long long sB2,
    long long sC1, long long sC2, int flags)
{
    constexpr int MFRAG = WM / 16;
    constexpr int NFRAG = WN / 8;
    constexpr int AIT = (128 * 8) / 256;   // 4
    constexpr int BIT = (BN * 8) / 256;    // 4 or 2

    __shared__ __align__(16) bf16 As[2][128][24];
    __shared__ __align__(16) bf16 Bs[2][BN][24];

    int z = blockIdx.z, zw = z / HB, zh = z % HB;
    Ah += zw * sA1 + zh * sA2;  Al += zw * sA1 + zh * sA2;
    Bh += zw * sB1 + zh * sB2;  Bl += zw * sB1 + zh * sB2;
    C  += zw * sC1 + zh * sC2;

    int bm = blockIdx.y * 128, bn = blockIdx.x * BN;
    int tid = threadIdx.x, lane = tid & 31, warp = tid >> 5;
    int wm = warp / WARPS_N, wn = warp % WARPS_N;
    int grp = lane >> 2, tig = lane & 3;

    float acc[MFRAG][NFRAG][4];
#pragma unroll
    for (int i = 0; i < MFRAG; i++)
#pragma unroll
        for (int j = 0; j < NFRAG; j++)
#pragma unroll
            for (int q = 0; q < 4; q++) acc[i][j][q] = 0.f;

    uint32_t aw[2][AIT], bw[2][BIT];

    auto stage = [&](int k0) {
        // K is even for every call site, so a k-pair never straddles K.
#pragma unroll
        for (int h = 0; h < 2; h++) {
            const bf16* src = h ? Al : Ah;
#pragma unroll
            for (int i = 0; i < AIT; i++) {
                int idx = tid + i * 256, row = idx >> 3, kp = idx & 7;
                int gm = bm + row, gk = k0 + kp * 2;
                uint32_t v = 0;
                if (gm < M && gk < K)
                    v = *(const uint32_t*)&src[(size_t)gm * lda + gk];
                aw[h][i] = v;
            }
        }
#pragma unroll
        for (int h = 0; h < 2; h++) {
            const bf16* src = h ? Bl : Bh;
#pragma unroll
            for (int i = 0; i < BIT; i++) {
                int idx = tid + i * 256, row = idx >> 3, kp = idx & 7;
                int gn = bn + row, gk = k0 + kp * 2;
                uint32_t v = 0;
                if (gn < N && gk < K)
                    v = *(const uint32_t*)&src[(size_t)gn * ldb + gk];
                bw[h][i] = v;
            }
        }
    };

    int ksteps = (K + 15) >> 4;
    stage(0);

    for (int ks = 0; ks < ksteps; ks++) {
        __syncthreads();
#pragma unroll
        for (int h = 0; h < 2; h++)
#pragma unroll
            for (int i = 0; i < AIT; i++) {
                int idx = tid + i * 256, row = idx >> 3, kp = idx & 7;
                *(uint32_t*)&As[h][row][kp * 2] = aw[h][i];
            }
#pragma unroll
        for (int h = 0; h < 2; h++)
#pragma unroll
            for (int i = 0; i < BIT; i++) {
                int idx = tid + i * 256, row = idx >> 3, kp = idx & 7;
                *(uint32_t*)&Bs[h][row][kp * 2] = bw[h][i];
            }
        __syncthreads();

        int kn = (ks + 1) << 4;
        if (kn < K) stage(kn);   // overlap next-tile global loads with mma

        uint32_t afh[MFRAG][4], afl[MFRAG][4], bfh[NFRAG][2], bfl[NFRAG][2];
#pragma unroll
        for (int mf = 0; mf < MFRAG; mf++) {
            int r = wm * WM + mf * 16 + grp;
            afh[mf][0] = *(const uint32_t*)&As[0][r][tig * 2];
            afh[mf][1] = *(const uint32_t*)&As[0][r + 8][tig * 2];
            afh[mf][2] = *(const uint32_t*)&As[0][r][tig * 2 + 8];
            afh[mf][3] = *(const uint32_t*)&As[0][r + 8][tig * 2 + 8];
            afl[mf][0] = *(const uint32_t*)&As[1][r][tig * 2];
            afl[mf][1] = *(const uint32_t*)&As[1][r + 8][tig * 2];
            afl[mf][2] = *(const uint32_t*)&As[1][r][tig * 2 + 8];
            afl[mf][3] = *(const uint32_t*)&As[1][r + 8][tig * 2 + 8];
        }
#pragma unroll
        for (int nf = 0; nf < NFRAG; nf++) {
            int c = wn * WN + nf * 8 + grp;
            bfh[nf][0] = *(const uint32_t*)&Bs[0][c][tig * 2];
            bfh[nf][1] = *(const uint32_t*)&Bs[0][c][tig * 2 + 8];
            bfl[nf][0] = *(const uint32_t*)&Bs[1][c][tig * 2];
            bfl[nf][1] = *(const uint32_t*)&Bs[1][c][tig * 2 + 8];
        }
#pragma unroll
        for (int mf = 0; mf < MFRAG; mf++)
#pragma unroll
            for (int nf = 0; nf < NFRAG; nf++) {
                MMA_BF16(acc[mf][nf], afh[mf], bfh[nf]);
                MMA_BF16(acc[mf][nf], afh[mf], bfl[nf]);
                MMA_BF16(acc[mf][nf], afl[mf], bfh[nf]);
            }
    }

    // epilogue
#pragma unroll
    for (int mf = 0; mf < MFRAG; mf++)
#pragma unroll
        for (int nf = 0; nf < NFRAG; nf++) {
            int r0 = bm + wm * WM + mf * 16 + grp;
            int c0 = bn + wn * WN + nf * 8 + tig * 2;
#pragma unroll
            for (int q = 0; q < 4; q++) {
                int r = r0 + (q >> 1) * 8;
                int c = c0 + (q & 1);
                if (r < M && c < N) {
                    float v = acc[mf][nf][q];
                    if (flags & GF_BIAS) v += bias[c];
                    if (flags & GF_GELU)
                        v = 0.5f * v * (1.f + erff(v * 0.70710678118654752f));
                    size_t o = (size_t)r * ldc + c;
                    if (flags & GF_ADD) v += C[o];
                    C[o] = v;
                }
            }
        }
}

// ---------------- conversions ------------------------------------------------
// n must be divisible by 4 (true for all call sites).
__global__ void conv_hilo_kernel(const float* __restrict__ in,
                                 bf16* __restrict__ hi, bf16* __restrict__ lo,
                                 long long n4)
{
    long long i = (long long)blockIdx.x * blockDim.x + threadIdx.x;
    if (i >= n4) return;
    float4 v = ((const float4*)in)[i];
    bf16 h0 = __float2bfloat16(v.x), h1 = __float2bfloat16(v.y);
    bf16 h2 = __float2bfloat16(v.z), h3 = __float2bfloat16(v.w);
    bf16 l0 = __float2bfloat16(v.x - __bfloat162float(h0));
    bf16 l1 = __float2bfloat16(v.y - __bfloat162float(h1));
    bf16 l2 = __float2bfloat16(v.z - __bfloat162float(h2));
    bf16 l3 = __float2bfloat16(v.w - __bfloat162float(h3));
    uint64_t hp, lp;
    ((bf16*)&hp)[0] = h0; ((bf16*)&hp)[1] = h1; ((bf16*)&hp)[2] = h2; ((bf16*)&hp)[3] = h3;
    ((bf16*)&lp)[0] = l0; ((bf16*)&lp)[1] = l1; ((bf16*)&lp)[2] = l2; ((bf16*)&lp)[3] = l3;
    ((uint64_t*)hi)[i] = hp;
    ((uint64_t*)lo)[i] = lp;
}

// W[K][N] fp32 (per-layer stride K*N) -> out[N][K] bf16 hi/lo
__global__ void tconv_kernel(const float* __restrict__ in,
                             bf16* __restrict__ ohi, bf16* __restrict__ olo,
                             int K, int N)
{
    __shared__ float tile[32][33];
    size_t zoff = (size_t)blockIdx.z * K * N;
    in += zoff; ohi += zoff; olo += zoff;
    int k0 = blockIdx.y * 32, n0 = blockIdx.x * 32;
#pragma unroll
    for (int i = 0; i < 4; i++) {
        int k = k0 + threadIdx.y + i * 8, n = n0 + threadIdx.x;
        tile[threadIdx.y + i * 8][threadIdx.x] =
            (k < K && n < N) ? in[(size_t)k * N + n] : 0.f;
    }
    __syncthreads();
#pragma unroll
    for (int i = 0; i < 4; i++) {
        int n = n0 + threadIdx.y + i * 8, k = k0 + threadIdx.x;
        if (n < N && k < K) {
            float v = tile[threadIdx.x][threadIdx.y + i * 8];
            bf16 h = __float2bfloat16(v);
            ohi[(size_t)n * K + k] = h;
            olo[(size_t)n * K + k] = __float2bfloat16(v - __bfloat162float(h));
        }
    }
}

// vT[z][d][n] = v from qkv (fp32), as bf16 hi/lo
__global__ void vt_kernel(const float* __restrict__ qkv,
                          bf16* __restrict__ vh, bf16* __restrict__ vl,
                          int N, int B)
{
    long long idx = (long long)blockIdx.x * blockDim.x + threadIdx.x;
    long long total = (long long)B * 64 * N;
    if (idx >= total) return;
    int n = (int)(idx % N);
    int d = (int)((idx / N) % 64);
    int z = (int)(idx / ((long long)64 * N));
    int zw = z / 12, zh = z % 12;
    float v = qkv[((size_t)zw * N + n) * 2304 + 1536 + zh * 64 + d];
    bf16 h = __float2bfloat16(v);
    vh[idx] = h;
    vl[idx] = __float2bfloat16(v - __bfloat162float(h));
}

// ---------------- LayerNorm --------------------------------------------------
__global__ void ln_kernel(const float* __restrict__ in, float* __restrict__ out,
                          const float* __restrict__ w, const float* __restrict__ bb,
                          int C, float eps)
{
    int row = blockIdx.x;
    const float* xr = in + (size_t)row * C;
    float* yr = out + (size_t)row * C;
    float s = 0.f, s2 = 0.f;
    for (int i = threadIdx.x; i < C; i += blockDim.x) {
        float v = xr[i]; s += v; s2 += v * v;
    }
    __shared__ float shs[8], shq[8];
#pragma unroll
    for (int o = 16; o > 0; o >>= 1) {
        s  += __shfl_down_sync(0xffffffffu, s, o);
        s2 += __shfl_down_sync(0xffffffffu, s2, o);
    }
    int wid = threadIdx.x >> 5;
    if ((threadIdx.x & 31) == 0) { shs[wid] = s; shq[wid] = s2; }
    __syncthreads();
    if (threadIdx.x == 0) {
        float a = 0.f, b2 = 0.f;
        for (int k = 0; k < 8; k++) { a += shs[k]; b2 += shq[k]; }
        shs[0] = a; shq[0] = b2;
    }
    __syncthreads();
    float mean = shs[0] / C;
    float var = shq[0] / C - mean * mean;
    float inv = rsqrtf(fmaxf(var, 0.f) + eps);
    for (int i = threadIdx.x; i < C; i += blockDim.x)
        yr[i] = (xr[i] - mean) * inv * w[i] + bb[i];
}

// ---------------- decomposed rel-pos dot products ----------------------------
__global__ void reldot_kernel(const float* __restrict__ qkv,
                              const float* __restrict__ table,
                              float* __restrict__ out,
                              int N, int W, int S, int mode, int B)
{
    long long idx = (long long)blockIdx.x * blockDim.x + threadIdx.x;
    long long total = (long long)B * N * S;
    if (idx >= total) return;
    int kk = (int)(idx % S);
    long long t = idx / S;
    int qi = (int)(t % N);
    int z = (int)(t / N);
    int qc = mode ? (qi % W) : (qi / W);
    const float* q = qkv + (size_t)(z / 12) * N * 2304 + (size_t)qi * 2304 + (z % 12) * 64;
    const float* r = table + (size_t)(qc - kk + S - 1) * 64;
    float acc = 0.f;
#pragma unroll
    for (int d = 0; d < 64; d++) acc += q[d] * r[d];
    out[idx] = acc;
}

// ---------------- softmax with fused scale + rel terms -----------------------
__global__ void softmax_rel_kernel(float* __restrict__ S,
                                   const float* __restrict__ relh,
                                   const float* __restrict__ relw,
                                   int N, int H, int W, float scale)
{
    int qi = blockIdx.x;
    int z = blockIdx.y;
    float* row = S + ((size_t)z * N + qi) * (size_t)N;
    const float* rh = relh + ((size_t)z * N + qi) * H;
    const float* rw = relw + ((size_t)z * N + qi) * W;

    __shared__ float sh[8];
    float mx = -1e30f;
    for (int i = threadIdx.x; i < N; i += blockDim.x) {
        float v = row[i] * scale + rh[i / W] + rw[i % W];
        row[i] = v;
        mx = fmaxf(mx, v);
    }
#pragma unroll
    for (int o = 16; o > 0; o >>= 1) mx = fmaxf(mx, __shfl_down_sync(0xffffffffu, mx, o));
    int wid = threadIdx.x >> 5;
    if ((threadIdx.x & 31) == 0) sh[wid] = mx;
    __syncthreads();
    if (threadIdx.x == 0) {
        float a = -1e30f;
        for (int k = 0; k < 8; k++) a = fmaxf(a, sh[k]);
        sh[0] = a;
    }
    __syncthreads();
    float m = sh[0];
    __syncthreads();

    float sum = 0.f;
    for (int i = threadIdx.x; i < N; i += blockDim.x) {
        float e = __expf(row[i] - m);
        row[i] = e;
        sum += e;
    }
#pragma unroll
    for (int o = 16; o > 0; o >>= 1) sum += __shfl_down_sync(0xffffffffu, sum, o);
    if ((threadIdx.x & 31) == 0) sh[wid] = sum;
    __syncthreads();
    if (threadIdx.x == 0) {
        float a = 0.f;
        for (int k = 0; k < 8; k++) a += sh[k];
        sh[0] = a;
    }
    __syncthreads();
    float inv = 1.f / sh[0];
    for (int i = threadIdx.x; i < N; i += blockDim.x) row[i] *= inv;
}

// ---------------- layout kernels ---------------------------------------------
__global__ void im2col_patch_kernel(const float* __restrict__ x, float* __restrict__ A)
{
    int idx = blockIdx.x * blockDim.x + threadIdx.x;
    if (idx >= 1024 * 768) return;
    int k = idx % 768, p = idx / 768;
    int c = k % 3, tkk = k / 3;
    int pw = tkk % 16, ph = tkk / 16;
    int py = p / 32, px = p % 32;
    A[idx] = x[(size_t)c * 512 * 512 + (size_t)(py * 16 + ph) * 512 + (px * 16 + pw)];
}

__global__ void winpart_kernel(const float* __restrict__ in, float* __restrict__ out)
{
    int idx = blockIdx.x * blockDim.x + threadIdx.x;
    if (idx >= 9 * 196 * 768) return;
    int c = idx % 768;
    int t = idx / 768;
    int n = t % 196, w = t / 196;
    int wy = n / 14, wx = n % 14;
    int wr = w / 3, wc = w % 3;
    int y = wr * 14 + wy, x = wc * 14 + wx;
    out[idx] = (y < 32 && x < 32) ? in[((size_t)y * 32 + x) * 768 + c] : 0.f;
}

__global__ void winunpart_kernel(const float* __restrict__ in, float* __restrict__ out)
{
    int idx = blockIdx.x * blockDim.x + threadIdx.x;
    if (idx >= 1024 * 768) return;
    int c = idx % 768;
    int t = idx / 768;
    int y = t / 32, x = t % 32;
    int w = (y / 14) * 3 + (x / 14);
    int n = (y % 14) * 14 + (x % 14);
    out[idx] = in[((size_t)w * 196 + n) * 768 + c];
}

__global__ void im2col3_kernel(const float* __restrict__ in, float* __restrict__ A)
{
    int idx = blockIdx.x * blockDim.x + threadIdx.x;
    if (idx >= 1024 * 2304) return;
    int k = idx % 2304, p = idx / 2304;
    int ic = k % 256, t = k / 256;
    int kx = t % 3, ky = t / 3;
    int y = p / 32 + ky - 1, x = p % 32 + kx - 1;
    A[idx] = (y >= 0 && y < 32 && x >= 0 && x < 32)
                 ? in[((size_t)y * 32 + x) * 256 + ic] : 0.f;
}

__global__ void transpose_out_kernel(const float* __restrict__ in, float* __restrict__ out)
{
    int idx = blockIdx.x * blockDim.x + threadIdx.x;
    if (idx >= 256 * 1024) return;
    int yx = idx % 1024, c = idx / 1024;
    out[idx] = in[(size_t)yx * 256 + c];
}

// ---------------- host orchestration -----------------------------------------
static inline void gemmb(const bf16* Ah, const bf16* Al,
                         const bf16* Bh, const bf16* Bl,
                         float* Cp, const float* bias,
                         int M, int N, int K, int lda, int ldb, int ldc,
                         int batches, int HB,
                         long long sA1, long long sA2, long long sB1, long long sB2,
                         long long sC1, long long sC2, int flags)
{
    if (N >= 128) {
        dim3 grid((N + 127) / 128, (M + 127) / 128, batches);
        gemm_mma_kernel<128, 2, 4, 64, 32><<<grid, 256>>>(
            Ah, Al, Bh, Bl, Cp, bias, M, N, K, lda, ldb, ldc,
            HB, sA1, sA2, sB1, sB2, sC1, sC2, flags);
    } else {
        dim3 grid((N + 63) / 64, (M + 127) / 128, batches);
        gemm_mma_kernel<64, 4, 2, 32, 32><<<grid, 256>>>(
            Ah, Al, Bh, Bl, Cp, bias, M, N, K, lda, ldb, ldc,
            HB, sA1, sA2, sB1, sB2, sC1, sC2, flags);
    }
}

extern "C" void kernel_launch(void* const* d_in, const int* in_sizes, int n_in,
                              void* d_out, int out_size)
{
    (void)in_sizes; (void)n_in; (void)out_size;
    const float* x       = (const float*)d_in[0];
    const float* patch_w = (const float*)d_in[1];
    const float* patch_b = (const float*)d_in[2];
    const float* pos     = (const float*)d_in[3];
    const float* ln1_w   = (const float*)d_in[4];
    const float* ln1_b   = (const float*)d_in[5];
    const float* qkv_w   = (const float*)d_in[6];
    const float* qkv_b   = (const float*)d_in[7];
    const float* proj_w  = (const float*)d_in[8];
    const float* proj_b  = (const float*)d_in[9];
    const float* ln2_w   = (const float*)d_in[10];
    const float* ln2_b   = (const float*)d_in[11];
    const float* fc1_w   = (const float*)d_in[12];
    const float* fc1_b   = (const float*)d_in[13];
    const float* fc2_w   = (const float*)d_in[14];
    const float* fc2_b   = (const float*)d_in[15];
    const float* rhw     = (const float*)d_in[16];
    const float* rww     = (const float*)d_in[17];
    const float* rhg     = (const float*)d_in[18];
    const float* rwg     = (const float*)d_in[19];
    const float* neck_w1 = (const float*)d_in[20];
    const float* nln1w   = (const float*)d_in[21];
    const float* nln1b   = (const float*)d_in[22];
    const float* neck_w2 = (const float*)d_in[23];
    const float* nln2w   = (const float*)d_in[24];
    const float* nln2b   = (const float*)d_in[25];

    float *A, *h, *t, *w, *qkv, *sc, *rh, *rw, *ao, *u, *mlp, *n1, *n2;
    cudaGetSymbolAddress((void**)&A,   g_A);
    cudaGetSymbolAddress((void**)&h,   g_h);
    cudaGetSymbolAddress((void**)&t,   g_t);
    cudaGetSymbolAddress((void**)&w,   g_w);
    cudaGetSymbolAddress((void**)&qkv, g_qkv);
    cudaGetSymbolAddress((void**)&sc,  g_sc);
    cudaGetSymbolAddress((void**)&rh,  g_rh);
    cudaGetSymbolAddress((void**)&rw,  g_rw);
    cudaGetSymbolAddress((void**)&ao,  g_ao);
    cudaGetSymbolAddress((void**)&u,   g_u);
    cudaGetSymbolAddress((void**)&mlp, g_mlp);
    cudaGetSymbolAddress((void**)&n1,  g_n1);
    cudaGetSymbolAddress((void**)&n2,  g_n2);

    bf16 *wqh, *wql, *wph, *wpl, *w1h, *w1l, *w2h, *w2l;
    bf16 *wpth, *wptl, *wn1h, *wn1l, *wn2h, *wn2l;
    bf16 *acth, *actl, *qbh, *qbl, *ath, *atl, *vth, *vtl;
    bf16 *colh, *coll, *mbh, *mbl, *ubh, *ubl;
    cudaGetSymbolAddress((void**)&wqh,  g_wq_h);  cudaGetSymbolAddress((void**)&wql,  g_wq_l);
    cudaGetSymbolAddress((void**)&wph,  g_wp_h);  cudaGetSymbolAddress((void**)&wpl,  g_wp_l);
    cudaGetSymbolAddress((void**)&w1h,  g_w1_h);  cudaGetSymbolAddress((void**)&w1l,  g_w1_l);
    cudaGetSymbolAddress((void**)&w2h,  g_w2_h);  cudaGetSymbolAddress((void**)&w2l,  g_w2_l);
    cudaGetSymbolAddress((void**)&wpth, g_wpt_h); cudaGetSymbolAddress((void**)&wptl, g_wpt_l);
    cudaGetSymbolAddress((void**)&wn1h, g_wn1_h); cudaGetSymbolAddress((void**)&wn1l, g_wn1_l);
    cudaGetSymbolAddress((void**)&wn2h, g_wn2_h); cudaGetSymbolAddress((void**)&wn2l, g_wn2_l);
    cudaGetSymbolAddress((void**)&acth, g_act_h); cudaGetSymbolAddress((void**)&actl, g_act_l);
    cudaGetSymbolAddress((void**)&qbh,  g_qb_h);  cudaGetSymbolAddress((void**)&qbl,  g_qb_l);
    cudaGetSymbolAddress((void**)&ath,  g_at_h);  cudaGetSymbolAddress((void**)&atl,  g_at_l);
    cudaGetSymbolAddress((void**)&vth,  g_vt_h);  cudaGetSymbolAddress((void**)&vtl,  g_vt_l);
    cudaGetSymbolAddress((void**)&colh, g_col_h); cudaGetSymbolAddress((void**)&coll, g_col_l);
    cudaGetSymbolAddress((void**)&mbh,  g_mb_h);  cudaGetSymbolAddress((void**)&mbl,  g_mb_l);
    cudaGetSymbolAddress((void**)&ubh,  g_ub_h);  cudaGetSymbolAddress((void**)&ubl,  g_ub_l);

    const int T = 256;
    dim3 tb(32, 8);
#define CONV(src, hib, lob, n) \
    conv_hilo_kernel<<<(unsigned)((((long long)(n) / 4) + T - 1) / T), T>>>( \
        src, hib, lob, (long long)(n) / 4)

    // ---- weight conversion (transpose to [N][K], split hi/lo) ----
    tconv_kernel<<<dim3(72, 24, 12), tb>>>(qkv_w,  wqh,  wql,  768, 2304);
    tconv_kernel<<<dim3(24, 24, 12), tb>>>(proj_w, wph,  wpl,  768, 768);
    tconv_kernel<<<dim3(96, 24, 12), tb>>>(fc1_w,  w1h,  w1l,  768, 3072);
    tconv_kernel<<<dim3(24, 96, 12), tb>>>(fc2_w,  w2h,  w2l,  3072, 768);
    tconv_kernel<<<dim3(24, 24, 1),  tb>>>(patch_w, wpth, wptl, 768, 768);
    tconv_kernel<<<dim3(8, 24, 1),   tb>>>(neck_w1, wn1h, wn1l, 768, 256);
    tconv_kernel<<<dim3(8, 72, 1),   tb>>>(neck_w2, wn2h, wn2l, 2304, 256);

    // ---- patch embed + pos_embed ----
    im2col_patch_kernel<<<(1024 * 768 + T - 1) / T, T>>>(x, A);
    CONV(A, colh, coll, 1024 * 768);
    cudaMemcpyAsync(h, pos, (size_t)1024 * 768 * sizeof(float),
                    cudaMemcpyDeviceToDevice, 0);
    gemmb(colh, coll, wpth, wptl, h, patch_b, 1024, 768, 768, 768, 768, 768,
          1, 1, 0, 0, 0, 0, 0, 0, GF_BIAS | GF_ADD);

    int wi = 0, gi = 0;
    for (int i = 0; i < 12; i++) {
        bool glob = (i == 2 || i == 5 || i == 8 || i == 11);
        int nw = glob ? 1 : 9;
        int N = glob ? 1024 : 196;
        int Hd = glob ? 32 : 14;
        int tokens = nw * N;
        int B = nw * 12;

        ln_kernel<<<1024, T>>>(h, t, ln1_w + i * 768, ln1_b + i * 768, 768, 1e-5f);

        const float* src = t;
        if (!glob) {
            winpart_kernel<<<(tokens * 768 + T - 1) / T, T>>>(t, w);
            src = w;
        }
        CONV(src, acth, actl, (long long)tokens * 768);

        // qkv
        gemmb(acth, actl, wqh + (size_t)i * 2304 * 768, wql + (size_t)i * 2304 * 768,
              qkv, qkv_b + (size_t)i * 2304, tokens, 2304, 768, 768, 768, 2304,
              1, 1, 0, 0, 0, 0, 0, 0, GF_BIAS);

        CONV(qkv, qbh, qbl, (long long)tokens * 2304);
        {
            long long tv = (long long)B * 64 * N;
            vt_kernel<<<(unsigned)((tv + T - 1) / T), T>>>(qkv, vth, vtl, N, B);
        }

        const float* th = glob ? rhg + (size_t)gi * 63 * 64 : rhw + (size_t)wi * 27 * 64;
        const float* twp = glob ? rwg + (size_t)gi * 63 * 64 : rww + (size_t)wi * 27 * 64;
        long long tot = (long long)B * N * Hd;
        reldot_kernel<<<(unsigned)((tot + T - 1) / T), T>>>(qkv, th, rh, N, Hd, Hd, 0, B);
        reldot_kernel<<<(unsigned)((tot + T - 1) / T), T>>>(qkv, twp, rw, N, Hd, Hd, 1, B);

        // scores = q @ k^T
        gemmb(qbh, qbl, qbh + 768, qbl + 768, sc, nullptr,
              N, N, 64, 2304, 2304, N,
              B, 12,
              (long long)N * 2304, 64, (long long)N * 2304, 64,
              12LL * N * N, (long long)N * N, 0);

        softmax_rel_kernel<<<dim3(N, B), T>>>(sc, rh, rw, N, Hd, Hd, 0.125f);

        CONV(sc, ath, atl, (long long)B * N * N);

        // attn @ v
        gemmb(ath, atl, vth, vtl, ao, nullptr,
              N, 64, N, N, N, 768,
              B, 12,
              12LL * N * N, (long long)N * N,
              12LL * 64 * N, 64LL * N,
              (long long)N * 768, 64, 0);

        const float* po = ao;
        if (!glob) {
            winunpart_kernel<<<(1024 * 768 + T - 1) / T, T>>>(ao, u);
            po = u;
        }
        CONV(po, ubh, ubl, 1024 * 768);
        gemmb(ubh, ubl, wph + (size_t)i * 768 * 768, wpl + (size_t)i * 768 * 768,
              h, proj_b + (size_t)i * 768, 1024, 768, 768, 768, 768, 768,
              1, 1, 0, 0, 0, 0, 0, 0, GF_BIAS | GF_ADD);

        // MLP
        ln_kernel<<<1024, T>>>(h, t, ln2_w + i * 768, ln2_b + i * 768, 768, 1e-5f);
        CONV(t, acth, actl, 1024 * 768);
        gemmb(acth, actl, w1h + (size_t)i * 3072 * 768, w1l + (size_t)i * 3072 * 768,
              mlp, fc1_b + (size_t)i * 3072, 1024, 3072, 768, 768, 768, 3072,
              1, 1, 0, 0, 0, 0, 0, 0, GF_BIAS | GF_GELU);
        CONV(mlp, mbh, mbl, 1024 * 3072);
        gemmb(mbh, mbl, w2h + (size_t)i * 768 * 3072, w2l + (size_t)i * 768 * 3072,
              h, fc2_b + (size_t)i * 768, 1024, 768, 3072, 3072, 3072, 768,
              1, 1, 0, 0, 0, 0, 0, 0, GF_BIAS | GF_ADD);

        if (glob) gi++; else wi++;
    }

    // ---- neck ----
    CONV(h, acth, actl, 1024 * 768);
    gemmb(acth, actl, wn1h, wn1l, n1, nullptr, 1024, 256, 768, 768, 768, 256,
          1, 1, 0, 0, 0, 0, 0, 0, 0);
    ln_kernel<<<1024, T>>>(n1, n2, nln1w, nln1b, 256, 1e-6f);
    im2col3_kernel<<<(1024 * 2304 + T - 1) / T, T>>>(n2, A);
    CONV(A, colh, coll, 1024 * 2304);
    gemmb(colh, coll, wn2h, wn2l, n1, nullptr, 1024, 256, 2304, 2304, 2304, 256,
          1, 1, 0, 0, 0, 0, 0, 0, 0);
    ln_kernel<<<1024, T>>>(n1, n2, nln2w, nln2b, 256, 1e-6f);
    transpose_out_kernel<<<(256 * 1024 + T - 1) / T, T>>>(n2, (float*)d_out);
#undef CONV
}

// round 6
// speedup vs baseline: 2.0433x; 1.2550x over previous
#include <cuda_runtime.h>
#include <cuda_bf16.h>
#include <math.h>
#include <stdint.h>

typedef __nv_bfloat16 bf16;

#define GF_BIAS 1
#define GF_ADD  2
#define GF_GELU 4

// ---------------- fp32 scratch ----------------------------------------------
__device__ float g_A[1024 * 2304];
__device__ float g_h[1024 * 768];
__device__ float g_t[1024 * 768];
__device__ float g_w[9 * 196 * 768];
__device__ float g_qkv[9 * 196 * 2304];
__device__ float g_sc[12 * 1024 * 1024];
__device__ float g_rh[12 * 1024 * 32];
__device__ float g_rw[12 * 1024 * 32];
__device__ float g_ao[9 * 196 * 768];
__device__ float g_u[1024 * 768];
__device__ float g_mlp[1024 * 3072];
__device__ float g_n1[1024 * 256];
__device__ float g_n2[1024 * 256];

// ---------------- bf16 hi/lo buffers ----------------------------------------
__device__ bf16 g_wq_h[12 * 2304 * 768],  g_wq_l[12 * 2304 * 768];
__device__ bf16 g_wp_h[12 * 768 * 768],   g_wp_l[12 * 768 * 768];
__device__ bf16 g_w1_h[12 * 3072 * 768],  g_w1_l[12 * 3072 * 768];
__device__ bf16 g_w2_h[12 * 768 * 3072],  g_w2_l[12 * 768 * 3072];
__device__ bf16 g_wpt_h[768 * 768],       g_wpt_l[768 * 768];
__device__ bf16 g_wn1_h[256 * 768],       g_wn1_l[256 * 768];
__device__ bf16 g_wn2_h[256 * 2304],      g_wn2_l[256 * 2304];
__device__ bf16 g_act_h[9 * 196 * 768],   g_act_l[9 * 196 * 768];
__device__ bf16 g_qb_h[9 * 196 * 2304],   g_qb_l[9 * 196 * 2304];
__device__ bf16 g_at_h[12 * 1024 * 1024], g_at_l[12 * 1024 * 1024];
__device__ bf16 g_vt_h[108 * 64 * 196],   g_vt_l[108 * 64 * 196];
__device__ bf16 g_col_h[1024 * 2304],     g_col_l[1024 * 2304];
__device__ bf16 g_mb_h[1024 * 3072],      g_mb_l[1024 * 3072];
__device__ bf16 g_ub_h[1024 * 768],       g_ub_l[1024 * 768];

// ---------------- PTX helpers -------------------------------------------------
#define MMA_BF16(c, a, b) \
    asm volatile("mma.sync.aligned.m16n8k16.row.col.f32.bf16.bf16.f32 " \
                 "{%0,%1,%2,%3}, {%4,%5,%6,%7}, {%8,%9}, {%0,%1,%2,%3};\n" \
                 : "+f"((c)[0]), "+f"((c)[1]), "+f"((c)[2]), "+f"((c)[3]) \
                 : "r"((a)[0]), "r"((a)[1]), "r"((a)[2]), "r"((a)[3]), \
                   "r"((b)[0]), "r"((b)[1]))

#define LDSM_X4(r0, r1, r2, r3, addr) \
    asm volatile("ldmatrix.sync.aligned.m8n8.x4.shared.b16 {%0,%1,%2,%3}, [%4];" \
                 : "=r"(r0), "=r"(r1), "=r"(r2), "=r"(r3) : "r"(addr))

#define CP_ASYNC8(dst, src, sz) \
    asm volatile("cp.async.ca.shared.global [%0], [%1], 8, %2;\n" \
                 :: "r"(dst), "l"(src), "r"(sz))
#define CP_COMMIT() asm volatile("cp.async.commit_group;\n" ::: "memory")
#define CP_WAIT0()  asm volatile("cp.async.wait_group 0;\n" ::: "memory")

__device__ __forceinline__ uint32_t smaddr(const void* p) {
    return (uint32_t)__cvta_generic_to_shared(p);
}

// ---------------- split-bf16 batched GEMM (ldmatrix + cp.async) --------------
// C[M,N] = A[M,K] * B^T; A layout [m][k] (lda halves), B layout [n][k] (ldb).
// acc = Ah*Bh + Ah*Bl + Al*Bh, fp32 accumulate.
// batch z: offset = (z/HB)*s1 + (z%HB)*s2 per operand.
// Shared tiles live in dynamic smem: As[2][2][128][40] then Bs[2][2][BN][40].
template <int BN, int WARPS_M, int WARPS_N, int WM, int WN>
__global__ __launch_bounds__(256) void gemm_mma_kernel(
    const bf16* __restrict__ Ah, const bf16* __restrict__ Al,
    const bf16* __restrict__ Bh, const bf16* __restrict__ Bl,
    float* __restrict__ C, const float* __restrict__ bias,
    int M, int N, int K, int lda, int ldb, int ldc,
    int HB, long long sA1, long long sA2, long long sB1, long long sB2,
    long long sC1, long long sC2, int flags)
{
    constexpr int MFRAG = WM / 16;
    constexpr int NFRAG = WN / 8;
    constexpr int AL = (128 * 8) / 256;   // cp.async per thread per h for A
    constexpr int BL = (BN * 8) / 256;    // for B

    extern __shared__ __align__(16) bf16 smp[];
    typedef bf16 ArowT[2][128][40];
    typedef bf16 BrowT[2][BN][40];
    ArowT* As = (ArowT*)smp;                             // As[buf][h][row][col]
    BrowT* Bs = (BrowT*)(smp + 2 * 2 * 128 * 40);        // Bs[buf][h][row][col]

    int z = blockIdx.z, zw = z / HB, zh = z % HB;
    Ah += zw * sA1 + zh * sA2;  Al += zw * sA1 + zh * sA2;
    Bh += zw * sB1 + zh * sB2;  Bl += zw * sB1 + zh * sB2;
    C  += zw * sC1 + zh * sC2;

    int bm = blockIdx.y * 128, bn = blockIdx.x * BN;
    int tid = threadIdx.x, lane = tid & 31, warp = tid >> 5;
    int wm = warp / WARPS_N, wn = warp % WARPS_N;
    int grp = lane >> 2, tig = lane & 3;

    float acc[MFRAG][NFRAG][4];
#pragma unroll
    for (int i = 0; i < MFRAG; i++)
#pragma unroll
        for (int j = 0; j < NFRAG; j++)
#pragma unroll
            for (int q = 0; q < 4; q++) acc[i][j][q] = 0.f;

    auto stage = [&](int k0, int buf) {
#pragma unroll
        for (int h = 0; h < 2; h++) {
            const bf16* srcb = h ? Al : Ah;
#pragma unroll
            for (int i = 0; i < AL; i++) {
                int idx = tid + i * 256, row = idx >> 3, seg = idx & 7;
                int gm = bm + row, gk = k0 + seg * 4;
                bool ok = (gm < M && gk < K);
                const bf16* s = ok ? (srcb + (size_t)gm * lda + gk) : srcb;
                uint32_t d = smaddr(&As[buf][h][row][seg * 4]);
                CP_ASYNC8(d, s, ok ? 8 : 0);
            }
        }
#pragma unroll
        for (int h = 0; h < 2; h++) {
            const bf16* srcb = h ? Bl : Bh;
#pragma unroll
            for (int i = 0; i < BL; i++) {
                int idx = tid + i * 256, row = idx >> 3, seg = idx & 7;
                int gn = bn + row, gk = k0 + seg * 4;
                bool ok = (gn < N && gk < K);
                const bf16* s = ok ? (srcb + (size_t)gn * ldb + gk) : srcb;
                uint32_t d = smaddr(&Bs[buf][h][row][seg * 4]);
                CP_ASYNC8(d, s, ok ? 8 : 0);
            }
        }
        CP_COMMIT();
    };

    int ksteps = (K + 31) >> 5;
    stage(0, 0);

    for (int ks = 0; ks < ksteps; ks++) {
        CP_WAIT0();
        __syncthreads();
        int buf = ks & 1;
        if (ks + 1 < ksteps) stage((ks + 1) << 5, buf ^ 1);

        int a_row_off = (lane & 7) + (lane & 8);
        int a_col_off = (lane & 16) ? 8 : 0;
        int b_row_off = (lane & 7) + ((lane & 16) ? 8 : 0);
        int b_col_off = (lane & 8) ? 8 : 0;

#pragma unroll
        for (int ksub = 0; ksub < 32; ksub += 16) {
            uint32_t afh[MFRAG][4], afl[MFRAG][4], bfh[NFRAG][2], bfl[NFRAG][2];
#pragma unroll
            for (int mf = 0; mf < MFRAG; mf++) {
                int r = wm * WM + mf * 16 + a_row_off;
                int c = ksub + a_col_off;
                LDSM_X4(afh[mf][0], afh[mf][1], afh[mf][2], afh[mf][3],
                        smaddr(&As[buf][0][r][c]));
                LDSM_X4(afl[mf][0], afl[mf][1], afl[mf][2], afl[mf][3],
                        smaddr(&As[buf][1][r][c]));
            }
#pragma unroll
            for (int nf = 0; nf < NFRAG; nf += 2) {
                int r = wn * WN + nf * 8 + b_row_off;
                int c = ksub + b_col_off;
                LDSM_X4(bfh[nf][0], bfh[nf][1], bfh[nf + 1][0], bfh[nf + 1][1],
                        smaddr(&Bs[buf][0][r][c]));
                LDSM_X4(bfl[nf][0], bfl[nf][1], bfl[nf + 1][0], bfl[nf + 1][1],
                        smaddr(&Bs[buf][1][r][c]));
            }
#pragma unroll
            for (int mf = 0; mf < MFRAG; mf++)
#pragma unroll
                for (int nf = 0; nf < NFRAG; nf++) {
                    MMA_BF16(acc[mf][nf], afh[mf], bfh[nf]);
                    MMA_BF16(acc[mf][nf], afh[mf], bfl[nf]);
                    MMA_BF16(acc[mf][nf], afl[mf], bfh[nf]);
                }
        }
        __syncthreads();
    }

    // epilogue
#pragma unroll
    for (int mf = 0; mf < MFRAG; mf++)
#pragma unroll
        for (int nf = 0; nf < NFRAG; nf++) {
            int r0 = bm + wm * WM + mf * 16 + grp;
            int c0 = bn + wn * WN + nf * 8 + tig * 2;
#pragma unroll
            for (int q = 0; q < 4; q++) {
                int r = r0 + (q >> 1) * 8;
                int c = c0 + (q & 1);
                if (r < M && c < N) {
                    float v = acc[mf][nf][q];
                    if (flags & GF_BIAS) v += bias[c];
                    if (flags & GF_GELU)
                        v = 0.5f * v * (1.f + erff(v * 0.70710678118654752f));
                    size_t o = (size_t)r * ldc + c;
                    if (flags & GF_ADD) v += C[o];
                    C[o] = v;
                }
            }
        }
}

// smem sizes for the two instantiations
static const int SMEM_G128 = (2 * 2 * 128 * 40 + 2 * 2 * 128 * 40) * (int)sizeof(bf16); // 81920
static const int SMEM_G64  = (2 * 2 * 128 * 40 + 2 * 2 * 64 * 40) * (int)sizeof(bf16);  // 61440

// ---------------- conversions ------------------------------------------------
__global__ void conv_hilo_kernel(const float* __restrict__ in,
                                 bf16* __restrict__ hi, bf16* __restrict__ lo,
                                 long long n4)
{
    long long i = (long long)blockIdx.x * blockDim.x + threadIdx.x;
    if (i >= n4) return;
    float4 v = ((const float4*)in)[i];
    bf16 h0 = __float2bfloat16(v.x), h1 = __float2bfloat16(v.y);
    bf16 h2 = __float2bfloat16(v.z), h3 = __float2bfloat16(v.w);
    bf16 l0 = __float2bfloat16(v.x - __bfloat162float(h0));
    bf16 l1 = __float2bfloat16(v.y - __bfloat162float(h1));
    bf16 l2 = __float2bfloat16(v.z - __bfloat162float(h2));
    bf16 l3 = __float2bfloat16(v.w - __bfloat162float(h3));
    uint64_t hp, lp;
    ((bf16*)&hp)[0] = h0; ((bf16*)&hp)[1] = h1; ((bf16*)&hp)[2] = h2; ((bf16*)&hp)[3] = h3;
    ((bf16*)&lp)[0] = l0; ((bf16*)&lp)[1] = l1; ((bf16*)&lp)[2] = l2; ((bf16*)&lp)[3] = l3;
    ((uint64_t*)hi)[i] = hp;
    ((uint64_t*)lo)[i] = lp;
}

// W[K][N] fp32 (per-layer stride K*N) -> out[N][K] bf16 hi/lo
__global__ void tconv_kernel(const float* __restrict__ in,
                             bf16* __restrict__ ohi, bf16* __restrict__ olo,
                             int K, int N)
{
    __shared__ float tile[32][33];
    size_t zoff = (size_t)blockIdx.z * K * N;
    in += zoff; ohi += zoff; olo += zoff;
    int k0 = blockIdx.y * 32, n0 = blockIdx.x * 32;
#pragma unroll
    for (int i = 0; i < 4; i++) {
        int k = k0 + threadIdx.y + i * 8, n = n0 + threadIdx.x;
        tile[threadIdx.y + i * 8][threadIdx.x] =
            (k < K && n < N) ? in[(size_t)k * N + n] : 0.f;
    }
    __syncthreads();
#pragma unroll
    for (int i = 0; i < 4; i++) {
        int n = n0 + threadIdx.y + i * 8, k = k0 + threadIdx.x;
        if (n < N && k < K) {
            float v = tile[threadIdx.x][threadIdx.y + i * 8];
            bf16 h = __float2bfloat16(v);
            ohi[(size_t)n * K + k] = h;
            olo[(size_t)n * K + k] = __float2bfloat16(v - __bfloat162float(h));
        }
    }
}

// vT[z][d][n] = v from qkv (fp32), as bf16 hi/lo
__global__ void vt_kernel(const float* __restrict__ qkv,
                          bf16* __restrict__ vh, bf16* __restrict__ vl,
                          int N, int B)
{
    long long idx = (long long)blockIdx.x * blockDim.x + threadIdx.x;
    long long total = (long long)B * 64 * N;
    if (idx >= total) return;
    int n = (int)(idx % N);
    int d = (int)((idx / N) % 64);
    int z = (int)(idx / ((long long)64 * N));
    int zw = z / 12, zh = z % 12;
    float v = qkv[((size_t)zw * N + n) * 2304 + 1536 + zh * 64 + d];
    bf16 h = __float2bfloat16(v);
    vh[idx] = h;
    vl[idx] = __float2bfloat16(v - __bfloat162float(h));
}

// ---------------- LayerNorm --------------------------------------------------
__global__ void ln_kernel(const float* __restrict__ in, float* __restrict__ out,
                          const float* __restrict__ w, const float* __restrict__ bb,
                          int C, float eps)
{
    int row = blockIdx.x;
    const float* xr = in + (size_t)row * C;
    float* yr = out + (size_t)row * C;
    float s = 0.f, s2 = 0.f;
    for (int i = threadIdx.x; i < C; i += blockDim.x) {
        float v = xr[i]; s += v; s2 += v * v;
    }
    __shared__ float shs[8], shq[8];
#pragma unroll
    for (int o = 16; o > 0; o >>= 1) {
        s  += __shfl_down_sync(0xffffffffu, s, o);
        s2 += __shfl_down_sync(0xffffffffu, s2, o);
    }
    int wid = threadIdx.x >> 5;
    if ((threadIdx.x & 31) == 0) { shs[wid] = s; shq[wid] = s2; }
    __syncthreads();
    if (threadIdx.x == 0) {
        float a = 0.f, b2 = 0.f;
        for (int k = 0; k < 8; k++) { a += shs[k]; b2 += shq[k]; }
        shs[0] = a; shq[0] = b2;
    }
    __syncthreads();
    float mean = shs[0] / C;
    float var = shq[0] / C - mean * mean;
    float inv = rsqrtf(fmaxf(var, 0.f) + eps);
    for (int i = threadIdx.x; i < C; i += blockDim.x)
        yr[i] = (xr[i] - mean) * inv * w[i] + bb[i];
}

// ---------------- decomposed rel-pos dot products ----------------------------
__global__ void reldot_kernel(const float* __restrict__ qkv,
                              const float* __restrict__ table,
                              float* __restrict__ out,
                              int N, int W, int S, int mode, int B)
{
    long long idx = (long long)blockIdx.x * blockDim.x + threadIdx.x;
    long long total = (long long)B * N * S;
    if (idx >= total) return;
    int kk = (int)(idx % S);
    long long t = idx / S;
    int qi = (int)(t % N);
    int z = (int)(t / N);
    int qc = mode ? (qi % W) : (qi / W);
    const float* q = qkv + (size_t)(z / 12) * N * 2304 + (size_t)qi * 2304 + (z % 12) * 64;
    const float* r = table + (size_t)(qc - kk + S - 1) * 64;
    float acc = 0.f;
#pragma unroll
    for (int d = 0; d < 64; d++) acc += q[d] * r[d];
    out[idx] = acc;
}

// ---------------- softmax (fused scale + rel) writing bf16 hi/lo -------------
__global__ void softmax_rel_kernel(float* __restrict__ S,
                                   const float* __restrict__ relh,
                                   const float* __restrict__ relw,
                                   bf16* __restrict__ oh, bf16* __restrict__ ol,
                                   int N, int H, int W, float scale)
{
    int qi = blockIdx.x;
    int z = blockIdx.y;
    size_t base = ((size_t)z * N + qi) * (size_t)N;
    float* row = S + base;
    const float* rh = relh + ((size_t)z * N + qi) * H;
    const float* rw = relw + ((size_t)z * N + qi) * W;

    __shared__ float sh[8];
    float mx = -1e30f;
    for (int i = threadIdx.x; i < N; i += blockDim.x) {
        float v = row[i] * scale + rh[i / W] + rw[i % W];
        row[i] = v;
        mx = fmaxf(mx, v);
    }
#pragma unroll
    for (int o = 16; o > 0; o >>= 1) mx = fmaxf(mx, __shfl_down_sync(0xffffffffu, mx, o));
    int wid = threadIdx.x >> 5;
    if ((threadIdx.x & 31) == 0) sh[wid] = mx;
    __syncthreads();
    if (threadIdx.x == 0) {
        float a = -1e30f;
        for (int k = 0; k < 8; k++) a = fmaxf(a, sh[k]);
        sh[0] = a;
    }
    __syncthreads();
    float m = sh[0];
    __syncthreads();

    float sum = 0.f;
    for (int i = threadIdx.x; i < N; i += blockDim.x) {
        float e = __expf(row[i] - m);
        row[i] = e;
        sum += e;
    }
#pragma unroll
    for (int o = 16; o > 0; o >>= 1) sum += __shfl_down_sync(0xffffffffu, sum, o);
    if ((threadIdx.x & 31) == 0) sh[wid] = sum;
    __syncthreads();
    if (threadIdx.x == 0) {
        float a = 0.f;
        for (int k = 0; k < 8; k++) a += sh[k];
        sh[0] = a;
    }
    __syncthreads();
    float inv = 1.f / sh[0];
    for (int i = threadIdx.x; i < N; i += blockDim.x) {
        float v = row[i] * inv;
        bf16 hh = __float2bfloat16(v);
        oh[base + i] = hh;
        ol[base + i] = __float2bfloat16(v - __bfloat162float(hh));
    }
}

// ---------------- layout kernels ---------------------------------------------
__global__ void im2col_patch_kernel(const float* __restrict__ x, float* __restrict__ A)
{
    int idx = blockIdx.x * blockDim.x + threadIdx.x;
    if (idx >= 1024 * 768) return;
    int k = idx % 768, p = idx / 768;
    int c = k % 3, tkk = k / 3;
    int pw = tkk % 16, ph = tkk / 16;
    int py = p / 32, px = p % 32;
    A[idx] = x[(size_t)c * 512 * 512 + (size_t)(py * 16 + ph) * 512 + (px * 16 + pw)];
}

__global__ void winpart_kernel(const float* __restrict__ in, float* __restrict__ out)
{
    int idx = blockIdx.x * blockDim.x + threadIdx.x;
    if (idx >= 9 * 196 * 768) return;
    int c = idx % 768;
    int t = idx / 768;
    int n = t % 196, w = t / 196;
    int wy = n / 14, wx = n % 14;
    int wr = w / 3, wc = w % 3;
    int y = wr * 14 + wy, x = wc * 14 + wx;
    out[idx] = (y < 32 && x < 32) ? in[((size_t)y * 32 + x) * 768 + c] : 0.f;
}

__global__ void winunpart_kernel(const float* __restrict__ in, float* __restrict__ out)
{
    int idx = blockIdx.x * blockDim.x + threadIdx.x;
    if (idx >= 1024 * 768) return;
    int c = idx % 768;
    int t = idx / 768;
    int y = t / 32, x = t % 32;
    int w = (y / 14) * 3 + (x / 14);
    int n = (y % 14) * 14 + (x % 14);
    out[idx] = in[((size_t)w * 196 + n) * 768 + c];
}

__global__ void im2col3_kernel(const float* __restrict__ in, float* __restrict__ A)
{
    int idx = blockIdx.x * blockDim.x + threadIdx.x;
    if (idx >= 1024 * 2304) return;
    int k = idx % 2304, p = idx / 2304;
    int ic = k % 256, t = k / 256;
    int kx = t % 3, ky = t / 3;
    int y = p / 32 + ky - 1, x = p % 32 + kx - 1;
    A[idx] = (y >= 0 && y < 32 && x >= 0 && x < 32)
                 ? in[((size_t)y * 32 + x) * 256 + ic] : 0.f;
}

__global__ void transpose_out_kernel(const float* __restrict__ in, float* __restrict__ out)
{
    int idx = blockIdx.x * blockDim.x + threadIdx.x;
    if (idx >= 256 * 1024) return;
    int yx = idx % 1024, c = idx / 1024;
    out[idx] = in[(size_t)yx * 256 + c];
}

// ---------------- host orchestration -----------------------------------------
static inline void gemmb(const bf16* Ah, const bf16* Al,
                         const bf16* Bh, const bf16* Bl,
                         float* Cp, const float* bias,
                         int M, int N, int K, int lda, int ldb, int ldc,
                         int batches, int HB,
                         long long sA1, long long sA2, long long sB1, long long sB2,
                         long long sC1, long long sC2, int flags)
{
    if (N >= 128) {
        cudaFuncSetAttribute(gemm_mma_kernel<128, 2, 4, 64, 32>,
                             cudaFuncAttributeMaxDynamicSharedMemorySize, SMEM_G128);
        dim3 grid((N + 127) / 128, (M + 127) / 128, batches);
        gemm_mma_kernel<128, 2, 4, 64, 32><<<grid, 256, SMEM_G128>>>(
            Ah, Al, Bh, Bl, Cp, bias, M, N, K, lda, ldb, ldc,
            HB, sA1, sA2, sB1, sB2, sC1, sC2, flags);
    } else {
        cudaFuncSetAttribute(gemm_mma_kernel<64, 4, 2, 32, 32>,
                             cudaFuncAttributeMaxDynamicSharedMemorySize, SMEM_G64);
        dim3 grid((N + 63) / 64, (M + 127) / 128, batches);
        gemm_mma_kernel<64, 4, 2, 32, 32><<<grid, 256, SMEM_G64>>>(
            Ah, Al, Bh, Bl, Cp, bias, M, N, K, lda, ldb, ldc,
            HB, sA1, sA2, sB1, sB2, sC1, sC2, flags);
    }
}

extern "C" void kernel_launch(void* const* d_in, const int* in_sizes, int n_in,
                              void* d_out, int out_size)
{
    (void)in_sizes; (void)n_in; (void)out_size;
    const float* x       = (const float*)d_in[0];
    const float* patch_w = (const float*)d_in[1];
    const float* patch_b = (const float*)d_in[2];
    const float* pos     = (const float*)d_in[3];
    const float* ln1_w   = (const float*)d_in[4];
    const float* ln1_b   = (const float*)d_in[5];
    const float* qkv_w   = (const float*)d_in[6];
    const float* qkv_b   = (const float*)d_in[7];
    const float* proj_w  = (const float*)d_in[8];
    const float* proj_b  = (const float*)d_in[9];
    const float* ln2_w   = (const float*)d_in[10];
    const float* ln2_b   = (const float*)d_in[11];
    const float* fc1_w   = (const float*)d_in[12];
    const float* fc1_b   = (const float*)d_in[13];
    const float* fc2_w   = (const float*)d_in[14];
    const float* fc2_b   = (const float*)d_in[15];
    const float* rhw     = (const float*)d_in[16];
    const float* rww     = (const float*)d_in[17];
    const float* rhg     = (const float*)d_in[18];
    const float* rwg     = (const float*)d_in[19];
    const float* neck_w1 = (const float*)d_in[20];
    const float* nln1w   = (const float*)d_in[21];
    const float* nln1b   = (const float*)d_in[22];
    const float* neck_w2 = (const float*)d_in[23];
    const float* nln2w   = (const float*)d_in[24];
    const float* nln2b   = (const float*)d_in[25];

    float *A, *h, *t, *w, *qkv, *sc, *rh, *rw, *ao, *u, *mlp, *n1, *n2;
    cudaGetSymbolAddress((void**)&A,   g_A);
    cudaGetSymbolAddress((void**)&h,   g_h);
    cudaGetSymbolAddress((void**)&t,   g_t);
    cudaGetSymbolAddress((void**)&w,   g_w);
    cudaGetSymbolAddress((void**)&qkv, g_qkv);
    cudaGetSymbolAddress((void**)&sc,  g_sc);
    cudaGetSymbolAddress((void**)&rh,  g_rh);
    cudaGetSymbolAddress((void**)&rw,  g_rw);
    cudaGetSymbolAddress((void**)&ao,  g_ao);
    cudaGetSymbolAddress((void**)&u,   g_u);
    cudaGetSymbolAddress((void**)&mlp, g_mlp);
    cudaGetSymbolAddress((void**)&n1,  g_n1);
    cudaGetSymbolAddress((void**)&n2,  g_n2);

    bf16 *wqh, *wql, *wph, *wpl, *w1h, *w1l, *w2h, *w2l;
    bf16 *wpth, *wptl, *wn1h, *wn1l, *wn2h, *wn2l;
    bf16 *acth, *actl, *qbh, *qbl, *ath, *atl, *vth, *vtl;
    bf16 *colh, *coll, *mbh, *mbl, *ubh, *ubl;
    cudaGetSymbolAddress((void**)&wqh,  g_wq_h);  cudaGetSymbolAddress((void**)&wql,  g_wq_l);
    cudaGetSymbolAddress((void**)&wph,  g_wp_h);  cudaGetSymbolAddress((void**)&wpl,  g_wp_l);
    cudaGetSymbolAddress((void**)&w1h,  g_w1_h);  cudaGetSymbolAddress((void**)&w1l,  g_w1_l);
    cudaGetSymbolAddress((void**)&w2h,  g_w2_h);  cudaGetSymbolAddress((void**)&w2l,  g_w2_l);
    cudaGetSymbolAddress((void**)&wpth, g_wpt_h); cudaGetSymbolAddress((void**)&wptl, g_wpt_l);
    cudaGetSymbolAddress((void**)&wn1h, g_wn1_h); cudaGetSymbolAddress((void**)&wn1l, g_wn1_l);
    cudaGetSymbolAddress((void**)&wn2h, g_wn2_h); cudaGetSymbolAddress((void**)&wn2l, g_wn2_l);
    cudaGetSymbolAddress((void**)&acth, g_act_h); cudaGetSymbolAddress((void**)&actl, g_act_l);
    cudaGetSymbolAddress((void**)&qbh,  g_qb_h);  cudaGetSymbolAddress((void**)&qbl,  g_qb_l);
    cudaGetSymbolAddress((void**)&ath,  g_at_h);  cudaGetSymbolAddress((void**)&atl,  g_at_l);
    cudaGetSymbolAddress((void**)&vth,  g_vt_h);  cudaGetSymbolAddress((void**)&vtl,  g_vt_l);
    cudaGetSymbolAddress((void**)&colh, g_col_h); cudaGetSymbolAddress((void**)&coll, g_col_l);
    cudaGetSymbolAddress((void**)&mbh,  g_mb_h);  cudaGetSymbolAddress((void**)&mbl,  g_mb_l);
    cudaGetSymbolAddress((void**)&ubh,  g_ub_h);  cudaGetSymbolAddress((void**)&ubl,  g_ub_l);

    const int T = 256;
    dim3 tb(32, 8);
#define CONV(src, hib, lob, n) \
    conv_hilo_kernel<<<(unsigned)((((long long)(n) / 4) + T - 1) / T), T>>>( \
        src, hib, lob, (long long)(n) / 4)

    // ---- weight conversion (transpose to [N][K], split hi/lo) ----
    tconv_kernel<<<dim3(72, 24, 12), tb>>>(qkv_w,  wqh,  wql,  768, 2304);
    tconv_kernel<<<dim3(24, 24, 12), tb>>>(proj_w, wph,  wpl,  768, 768);
    tconv_kernel<<<dim3(96, 24, 12), tb>>>(fc1_w,  w1h,  w1l,  768, 3072);
    tconv_kernel<<<dim3(24, 96, 12), tb>>>(fc2_w,  w2h,  w2l,  3072, 768);
    tconv_kernel<<<dim3(24, 24, 1),  tb>>>(patch_w, wpth, wptl, 768, 768);
    tconv_kernel<<<dim3(8, 24, 1),   tb>>>(neck_w1, wn1h, wn1l, 768, 256);
    tconv_kernel<<<dim3(8, 72, 1),   tb>>>(neck_w2, wn2h, wn2l, 2304, 256);

    // ---- patch embed + pos_embed ----
    im2col_patch_kernel<<<(1024 * 768 + T - 1) / T, T>>>(x, A);
    CONV(A, colh, coll, 1024 * 768);
    cudaMemcpyAsync(h, pos, (size_t)1024 * 768 * sizeof(float),
                    cudaMemcpyDeviceToDevice, 0);
    gemmb(colh, coll, wpth, wptl, h, patch_b, 1024, 768, 768, 768, 768, 768,
          1, 1, 0, 0, 0, 0, 0, 0, GF_BIAS | GF_ADD);

    int wi = 0, gi = 0;
    for (int i = 0; i < 12; i++) {
        bool glob = (i == 2 || i == 5 || i == 8 || i == 11);
        int nw = glob ? 1 : 9;
        int N = glob ? 1024 : 196;
        int Hd = glob ? 32 : 14;
        int tokens = nw * N;
        int B = nw * 12;

        ln_kernel<<<1024, T>>>(h, t, ln1_w + i * 768, ln1_b + i * 768, 768, 1e-5f);

        const float* src = t;
        if (!glob) {
            winpart_kernel<<<(tokens * 768 + T - 1) / T, T>>>(t, w);
            src = w;
        }
        CONV(src, acth, actl, (long long)tokens * 768);

        // qkv
        gemmb(acth, actl, wqh + (size_t)i * 2304 * 768, wql + (size_t)i * 2304 * 768,
              qkv, qkv_b + (size_t)i * 2304, tokens, 2304, 768, 768, 768, 2304,
              1, 1, 0, 0, 0, 0, 0, 0, GF_BIAS);

        CONV(qkv, qbh, qbl, (long long)tokens * 2304);
        {
            long long tv = (long long)B * 64 * N;
            vt_kernel<<<(unsigned)((tv + T - 1) / T), T>>>(qkv, vth, vtl, N, B);
        }

        const float* th = glob ? rhg + (size_t)gi * 63 * 64 : rhw + (size_t)wi * 27 * 64;
        const float* twp = glob ? rwg + (size_t)gi * 63 * 64 : rww + (size_t)wi * 27 * 64;
        long long tot = (long long)B * N * Hd;
        reldot_kernel<<<(unsigned)((tot + T - 1) / T), T>>>(qkv, th, rh, N, Hd, Hd, 0, B);
        reldot_kernel<<<(unsigned)((tot + T - 1) / T), T>>>(qkv, twp, rw, N, Hd, Hd, 1, B);

        // scores = q @ k^T
        gemmb(qbh, qbl, qbh + 768, qbl + 768, sc, nullptr,
              N, N, 64, 2304, 2304, N,
              B, 12,
              (long long)N * 2304, 64, (long long)N * 2304, 64,
              12LL * N * N, (long long)N * N, 0);

        // softmax writes attention probs directly as bf16 hi/lo
        softmax_rel_kernel<<<dim3(N, B), T>>>(sc, rh, rw, ath, atl, N, Hd, Hd, 0.125f);

        // attn @ v
        gemmb(ath, atl, vth, vtl, ao, nullptr,
              N, 64, N, N, N, 768,
              B, 12,
              12LL * N * N, (long long)N * N,
              12LL * 64 * N, 64LL * N,
              (long long)N * 768, 64, 0);

        const float* po = ao;
        if (!glob) {
            winunpart_kernel<<<(1024 * 768 + T - 1) / T, T>>>(ao, u);
            po = u;
        }
        CONV(po, ubh, ubl, 1024 * 768);
        gemmb(ubh, ubl, wph + (size_t)i * 768 * 768, wpl + (size_t)i * 768 * 768,
              h, proj_b + (size_t)i * 768, 1024, 768, 768, 768, 768, 768,
              1, 1, 0, 0, 0, 0, 0, 0, GF_BIAS | GF_ADD);

        // MLP
        ln_kernel<<<1024, T>>>(h, t, ln2_w + i * 768, ln2_b + i * 768, 768, 1e-5f);
        CONV(t, acth, actl, 1024 * 768);
        gemmb(acth, actl, w1h + (size_t)i * 3072 * 768, w1l + (size_t)i * 3072 * 768,
              mlp, fc1_b + (size_t)i * 3072, 1024, 3072, 768, 768, 768, 3072,
              1, 1, 0, 0, 0, 0, 0, 0, GF_BIAS | GF_GELU);
        CONV(mlp, mbh, mbl, 1024 * 3072);
        gemmb(mbh, mbl, w2h + (size_t)i * 768 * 3072, w2l + (size_t)i * 768 * 3072,
              h, fc2_b + (size_t)i * 768, 1024, 768, 3072, 3072, 3072, 768,
              1, 1, 0, 0, 0, 0, 0, 0, GF_BIAS | GF_ADD);

        if (glob) gi++; else wi++;
    }

    // ---- neck ----
    CONV(h, acth, actl, 1024 * 768);
    gemmb(acth, actl, wn1h, wn1l, n1, nullptr, 1024, 256, 768, 768, 768, 256,
          1, 1, 0, 0, 0, 0, 0, 0, 0);
    ln_kernel<<<1024, T>>>(n1, n2, nln1w, nln1b, 256, 1e-6f);
    im2col3_kernel<<<(1024 * 2304 + T - 1) / T, T>>>(n2, A);
    CONV(A, colh, coll, 1024 * 2304);
    gemmb(colh, coll, wn2h, wn2l, n1, nullptr, 1024, 256, 2304, 2304, 2304, 256,
          1, 1, 0, 0, 0, 0, 0, 0, 0);
    ln_kernel<<<1024, T>>>(n1, n2, nln2w, nln2b, 256, 1e-6f);
    transpose_out_kernel<<<(256 * 1024 + T - 1) / T, T>>>(n2, (float*)d_out);
#undef CONV
}